// round 16
// baseline (speedup 1.0000x reference)
#include <cuda_runtime.h>

// EnhancedLIFNeuron on GB300 — two-kernel split.
// K1: streaming column-sum over t -> closed-form conv mean -> attention scale
//     (134 MB pure read at stream speed; leaves x hot in L2; writes 1 MB scales).
// K2: LIF scan (R8 phase-2 structure): 4 chains/thread as 2 packed f32x2 pairs,
//     x re-read via .cs ring (L2-hot from K1), spikes via st.global.cs.

#define Tn 128
#define Fn 2048
#define Bn 128

typedef unsigned long long u64;

__device__ float4 d_scale[(Bn * Fn) / 4];   // per-quad attention scales (1 MB)

__device__ __forceinline__ u64 pk(float lo, float hi) {
    u64 r; asm("mov.b64 %0,{%1,%2};" : "=l"(r) : "f"(lo), "f"(hi)); return r;
}
__device__ __forceinline__ void upk(u64 v, float& lo, float& hi) {
    asm("mov.b64 {%0,%1},%2;" : "=f"(lo), "=f"(hi) : "l"(v));
}
__device__ __forceinline__ u64 f2fma(u64 a, u64 b, u64 c) {
    u64 d; asm("fma.rn.f32x2 %0,%1,%2,%3;" : "=l"(d) : "l"(a), "l"(b), "l"(c)); return d;
}
__device__ __forceinline__ u64 f2mul(u64 a, u64 b) {
    u64 d; asm("mul.rn.f32x2 %0,%1,%2;" : "=l"(d) : "l"(a), "l"(b)); return d;
}
__device__ __forceinline__ u64 f2add(u64 a, u64 b) {
    u64 d; asm("add.rn.f32x2 %0,%1,%2;" : "=l"(d) : "l"(a), "l"(b)); return d;
}
__device__ __forceinline__ float frcp_ap(float a) {
    float r; asm("rcp.approx.ftz.f32 %0,%1;" : "=f"(r) : "f"(a)); return r;
}
__device__ __forceinline__ float fsqrt_ap(float a) {
    float r; asm("sqrt.approx.ftz.f32 %0,%1;" : "=f"(r) : "f"(a)); return r;
}
__device__ __forceinline__ float4 ld_once4(const float4* p) {   // streaming read
    float4 v;
    asm("ld.global.cs.v4.f32 {%0,%1,%2,%3},[%4];"
        : "=f"(v.x), "=f"(v.y), "=f"(v.z), "=f"(v.w) : "l"(p));
    return v;
}
__device__ __forceinline__ void st_stream2(ulonglong2* p, u64 a, u64 b) {
    asm volatile("st.global.cs.v2.u64 [%0],{%1,%2};" :: "l"(p), "l"(a), "l"(b) : "memory");
}

#define SMASK 0x8000000080000000ull

// ---------------- K1: sums -> attention scales ----------------
__global__ __launch_bounds__(128)
void sum_kernel(const float* __restrict__ x,
                const float* __restrict__ convw,
                const float* __restrict__ convb,
                const float* __restrict__ sap)
{
    const int cid = blockIdx.x * 128 + threadIdx.x;
    const int b   = cid >> 9;
    const int fq  = cid & 511;
    const float4* __restrict__ px4 =
        reinterpret_cast<const float4*>(x + (size_t)b * Tn * Fn) + fq;

    const float w0 = __ldg(convw + 0), w1 = __ldg(convw + 1), w2 = __ldg(convw + 2),
                w3 = __ldg(convw + 3), w4 = __ldg(convw + 4);
    const float cb = __ldg(convb);
    const float sa = __ldg(sap);

    u64 aA0 = 0, aA1 = 0, aB0 = 0, aB1 = 0;
    #pragma unroll 4
    for (int t = 0; t < Tn; t += 8) {
        float4 v0 = __ldg(px4 + (t + 0) * 512);
        float4 v1 = __ldg(px4 + (t + 1) * 512);
        float4 v2 = __ldg(px4 + (t + 2) * 512);
        float4 v3 = __ldg(px4 + (t + 3) * 512);
        float4 v4 = __ldg(px4 + (t + 4) * 512);
        float4 v5 = __ldg(px4 + (t + 5) * 512);
        float4 v6 = __ldg(px4 + (t + 6) * 512);
        float4 v7 = __ldg(px4 + (t + 7) * 512);
        aA0 = f2add(aA0, f2add(pk(v0.x, v0.y), pk(v4.x, v4.y)));
        aB0 = f2add(aB0, f2add(pk(v0.z, v0.w), pk(v4.z, v4.w)));
        aA1 = f2add(aA1, f2add(pk(v1.x, v1.y), pk(v5.x, v5.y)));
        aB1 = f2add(aB1, f2add(pk(v1.z, v1.w), pk(v5.z, v5.w)));
        aA0 = f2add(aA0, f2add(pk(v2.x, v2.y), pk(v6.x, v6.y)));
        aB0 = f2add(aB0, f2add(pk(v2.z, v2.w), pk(v6.z, v6.w)));
        aA1 = f2add(aA1, f2add(pk(v3.x, v3.y), pk(v7.x, v7.y)));
        aB1 = f2add(aB1, f2add(pk(v3.z, v3.w), pk(v7.z, v7.w)));
    }
    float sA0, sA1, sB0, sB1;
    upk(f2add(aA0, aA1), sA0, sA1);
    upk(f2add(aB0, aB1), sB0, sB1);

    float4 r0   = __ldg(px4 + 0 * 512);
    float4 r1   = __ldg(px4 + 1 * 512);
    float4 r126 = __ldg(px4 + 126 * 512);
    float4 r127 = __ldg(px4 + 127 * 512);

    const float W   = ((w0 + w1) + w2) + (w3 + w4);
    const float c34 = w3 + w4, c01 = w0 + w1;
#define MEANL(S, X0, X1, X126, X127) \
    ((W * (S) - c34 * (X0) - w4 * (X1) - w0 * (X126) - c01 * (X127)) * (1.0f/Tn) + cb)
    float m0 = MEANL(sA0, r0.x, r1.x, r126.x, r127.x);
    float m1 = MEANL(sA1, r0.y, r1.y, r126.y, r127.y);
    float m2 = MEANL(sB0, r0.z, r1.z, r126.z, r127.z);
    float m3 = MEANL(sB1, r0.w, r1.w, r126.w, r127.w);
#undef MEANL
    float4 sc;
    sc.x = 1.0f + 0.5f / (1.0f + __expf(-sa * m0));   // GAMMA = 0.5
    sc.y = 1.0f + 0.5f / (1.0f + __expf(-sa * m1));
    sc.z = 1.0f + 0.5f / (1.0f + __expf(-sa * m2));
    sc.w = 1.0f + 0.5f / (1.0f + __expf(-sa * m3));
    d_scale[cid] = sc;
}

// ---------------- K2: LIF scan ----------------
__global__ __launch_bounds__(128, 4)
void lif_kernel(const float* __restrict__ x,
                const float* __restrict__ thr0p,
                const float* __restrict__ convw,
                const float* __restrict__ convb,
                float* __restrict__ out)
{
    const int cid = blockIdx.x * 128 + threadIdx.x;   // quad-chain id
    const int b   = cid >> 9;
    const int fq  = cid & 511;
    const float4* __restrict__ px4 =
        reinterpret_cast<const float4*>(x + (size_t)b * Tn * Fn) + fq;

    const float thr0 = __ldg(thr0p);
    const float w0 = __ldg(convw + 0), w1 = __ldg(convw + 1), w2 = __ldg(convw + 2),
                w3 = __ldg(convw + 3), w4 = __ldg(convw + 4);
    const float cb = __ldg(convb);

    const float4 sc = d_scale[cid];
    const float sc0 = sc.x, sc1 = sc.y, sc2 = sc.z, sc3 = sc.w;

    // scaled conv weights, packed per pair
    const u64 VA0 = pk(w0*sc0, w0*sc1), VB0 = pk(w0*sc2, w0*sc3);
    const u64 VA1 = pk(w1*sc0, w1*sc1), VB1 = pk(w1*sc2, w1*sc3);
    const u64 VA2 = pk(w2*sc0, w2*sc1), VB2 = pk(w2*sc2, w2*sc3);
    const u64 VA3 = pk(w3*sc0, w3*sc1), VB3 = pk(w3*sc2, w3*sc3);
    const u64 VA4 = pk(w4*sc0, w4*sc1), VB4 = pk(w4*sc2, w4*sc3);
    const u64 VAb = pk(cb*sc0, cb*sc1), VBb = pk(cb*sc2, cb*sc3);

    // packed constants
    const float PI = 3.14159265358979323846f;
    const float INVPI = 1.0f / PI;
    const u64 DEC  = pk(0.9f, 0.9f);                  // DECAY == ALPHA
    const u64 CARG = pk(PI*0.5f, PI*0.5f);
    const u64 QRT  = pk(0.25f, 0.25f);
    const u64 ONE  = pk(1.0f, 1.0f);
    const u64 CAVG = pk(0.1f/3.0f, 0.1f/3.0f);
    const u64 CT0  = pk(0.1f*thr0, 0.1f*thr0);
    const u64 P0 = pk( 0.9998660f*INVPI,  0.9998660f*INVPI);
    const u64 P1 = pk(-0.3302995f*INVPI, -0.3302995f*INVPI);
    const u64 P2 = pk( 0.1801410f*INVPI,  0.1801410f*INVPI);
    const u64 P3 = pk(-0.0851330f*INVPI, -0.0851330f*INVPI);
    const u64 P4 = pk( 0.0208351f*INVPI,  0.0208351f*INVPI);

    // boundary rows (L2-hot from K1)
    float4 r0 = __ldg(px4 + 0 * 512);
    float4 r1 = __ldg(px4 + 1 * 512);
    float4 r2 = __ldg(px4 + 2 * 512);

    // LIF state, two packed pairs (A = f,f+1 ; B = f+2,f+3)
    u64 memA = 0, thrA = pk(thr0, thr0), h2A = 0, h12A = 0;
    u64 memB = 0, thrB = pk(thr0, thr0), h2B = 0, h12B = 0;
    u64 am2 = 0, am1 = 0, ac = pk(r0.x, r0.y), ap1 = pk(r1.x, r1.y), ap2 = pk(r2.x, r2.y);
    u64 bm2 = 0, bm1 = 0, bc = pk(r0.z, r0.w), bp1 = pk(r1.z, r1.w), bp2 = pk(r2.z, r2.w);

    float4 q0 = ld_once4(px4 + 3*512);
    float4 q1 = ld_once4(px4 + 4*512);
    float4 q2 = ld_once4(px4 + 5*512);
    float4 q3 = ld_once4(px4 + 6*512);
    const float4 z4 = make_float4(0.f, 0.f, 0.f, 0.f);

    ulonglong2* __restrict__ opp =
        reinterpret_cast<ulonglong2*>(out + (size_t)b * Tn * Fn) + fq;

#define PAIRSTEP(mem, thr, h2, h12, xm2, xm1, xc, xp1, xp2, V0,V1,V2,V3,V4,Vb, XNEW, SPK) \
    do {                                                                     \
        u64 cv = f2fma(V0, xm2, f2fma(V1, xm1, f2fma(V2, xc,                 \
                 f2fma(V3, xp1, f2fma(V4, xp2, Vb)))));                      \
        mem = f2fma(DEC, mem, cv);                                           \
        u64 z  = f2mul(f2add(mem, thr ^ SMASK), CARG);                       \
        u64 o  = f2fma(z, z, ONE);                                           \
        float olo, ohi; upk(o, olo, ohi);                                    \
        float rlo = frcp_ap(1.0f + fsqrt_ap(olo));                           \
        float rhi = frcp_ap(1.0f + fsqrt_ap(ohi));                           \
        u64 tq = f2mul(z, pk(rlo, rhi));                                     \
        u64 tt = f2mul(tq, tq);                                              \
        u64 p  = f2fma(f2fma(f2fma(f2fma(P4, tt, P3), tt, P2), tt, P1), tt, P0); \
        u64 spike = f2fma(tq, p, QRT);                                       \
        u64 s3 = f2add(h12, spike);                                          \
        thr = f2fma(DEC, thr, f2fma(CAVG, s3, CT0));                         \
        mem = f2fma(spike ^ SMASK, thr, mem);                                \
        h12 = f2add(h2, spike); h2 = spike;                                  \
        xm2 = xm1; xm1 = xc; xc = xp1; xp1 = xp2; xp2 = (XNEW);              \
        SPK = spike;                                                         \
    } while (0)

#define QSTEP(Q) do {                                                        \
        u64 spA, spB;                                                        \
        PAIRSTEP(memA, thrA, h2A, h12A, am2, am1, ac, ap1, ap2,              \
                 VA0,VA1,VA2,VA3,VA4,VAb, pk((Q).x,(Q).y), spA);             \
        PAIRSTEP(memB, thrB, h2B, h12B, bm2, bm1, bc, bp1, bp2,              \
                 VB0,VB1,VB2,VB3,VB4,VBb, pk((Q).z,(Q).w), spB);             \
        st_stream2(opp, spA, spB); opp += 512;                               \
    } while (0)

    for (int g = 0; g < Tn; g += 4) {
        int tb = g + 7;   // prefetch 4-7 steps ahead
        float4 n0 = (tb + 0 < Tn) ? ld_once4(px4 + (tb + 0) * 512) : z4;
        float4 n1 = (tb + 1 < Tn) ? ld_once4(px4 + (tb + 1) * 512) : z4;
        float4 n2 = (tb + 2 < Tn) ? ld_once4(px4 + (tb + 2) * 512) : z4;
        float4 n3 = (tb + 3 < Tn) ? ld_once4(px4 + (tb + 3) * 512) : z4;

        QSTEP(q0); QSTEP(q1); QSTEP(q2); QSTEP(q3);

        q0 = n0; q1 = n1; q2 = n2; q3 = n3;
    }
#undef QSTEP
#undef PAIRSTEP

    st_stream2(reinterpret_cast<ulonglong2*>(out + (size_t)Bn * Tn * Fn + (size_t)b * Fn) + fq,
               memA, memB);
}

extern "C" void kernel_launch(void* const* d_in, const int* in_sizes, int n_in,
                              void* d_out, int out_size)
{
    (void)in_sizes; (void)n_in; (void)out_size;
    const float* x    = (const float*)d_in[0];
    const float* thr0 = (const float*)d_in[1];
    const float* cw   = (const float*)d_in[2];
    const float* cbp  = (const float*)d_in[3];
    const float* sa   = (const float*)d_in[4];
    float* out = (float*)d_out;

    const int grid = (Bn * Fn) / (128 * 4);   // 512
    sum_kernel<<<grid, 128>>>(x, cw, cbp, sa);
    lif_kernel<<<grid, 128>>>(x, thr0, cw, cbp, out);
}